// round 9
// baseline (speedup 1.0000x reference)
#include <cuda_runtime.h>
#include <cuda_bf16.h>
#include <cuda_fp16.h>
#include <mma.h>
#include <math.h>
#include <stdint.h>

using namespace nvcuda;

#define N_NODES 50000
#define M_PAD   50048
#define N_EDGES 400000
#define NE_TOT  (N_EDGES + N_NODES)
#define F_IN    128
#define HID     64
#define HEADS   8
#define FEAT    (HEADS * HID)          // 512
#define N_CLASSES 16
#define NEG_SLOPE 0.2f

// ---------------------------------------------------------------------------
// Static scratch
// ---------------------------------------------------------------------------
__device__ __half g_x16 [(size_t)M_PAD * F_IN];
__device__ __half g_O16 [(size_t)M_PAD * FEAT];
__device__ __half g_h16 [(size_t)M_PAD * FEAT];
__device__ __half g_W0h [F_IN * FEAT];
__device__ __half g_W1h [FEAT * FEAT];
__device__ __half g_W2h [FEAT * N_CLASSES];
__device__ float  g_H2  [(size_t)M_PAD * N_CLASSES];
__device__ float  g_als [(size_t)N_NODES * HEADS];
__device__ float  g_ald [(size_t)N_NODES * HEADS];
__device__ int    g_deg   [N_NODES];
__device__ int    g_rowptr[N_NODES + 1];
__device__ int    g_cursor[N_NODES];
__device__ int    g_col   [NE_TOT];
__device__ int    g_bsum  [256];
__device__ int    g_is64;

__device__ __forceinline__ float eluf(float x)   { return x > 0.f ? x : expm1f(x); }
__device__ __forceinline__ float lrelu(float x)  { return x > 0.f ? x : NEG_SLOPE * x; }
__device__ __forceinline__ int clampi(int v) {
    return (v < 0) ? 0 : (v >= N_NODES ? N_NODES - 1 : v);
}
__device__ __forceinline__ int edge_at(const void* ei, int idx, int is64) {
    if (is64) return clampi((int)((const long long*)ei)[idx]);
    return clampi(((const int*)ei)[idx]);
}

__device__ __forceinline__ void cp_async16(uint32_t saddr, const void* gptr, int src_bytes) {
    asm volatile("cp.async.cg.shared.global [%0], [%1], 16, %2;\n"
                 :: "r"(saddr), "l"(gptr), "r"(src_bytes));
}
__device__ __forceinline__ void cp_commit() {
    asm volatile("cp.async.commit_group;\n");
}

// ---------------------------------------------------------------------------
// Setup kernel: fp16 conversions (x, W0, W1, W2) + deg zeroing + dtype probe.
// One launch so the big GEMM lands at launch index 5 for the ncu window.
// ---------------------------------------------------------------------------
#define NX4  (N_NODES * F_IN / 4)            // 1,600,000
#define NW04 (F_IN * FEAT / 4)               // 16,384
#define NW14 (FEAT * FEAT / 4)               // 65,536
#define NW24 (FEAT * N_CLASSES / 4)          // 2,048
#define NSET (NX4 + NW04 + NW14 + NW24 + N_NODES)

__device__ __forceinline__ void cvt4(const float* s, __half* d, int i4) {
    float4 v = *(const float4*)(s + i4);
    *(__half2*)(d + i4)     = __floats2half2_rn(v.x, v.y);
    *(__half2*)(d + i4 + 2) = __floats2half2_rn(v.z, v.w);
}

__global__ void setup_kernel(const float* __restrict__ x,
                             const float* __restrict__ W0,
                             const float* __restrict__ W1,
                             const float* __restrict__ W2,
                             const int* __restrict__ ei_raw)
{
    int i = blockIdx.x * blockDim.x + threadIdx.x;
    if (i == 0) {
        int any_nonzero = 0;
        #pragma unroll 1
        for (int k = 0; k < 64; k++) any_nonzero |= ei_raw[2 * k + 1];
        g_is64 = (any_nonzero == 0) ? 1 : 0;
    }
    if (i < NX4) { cvt4(x, g_x16, i << 2); return; }
    i -= NX4;
    if (i < NW04) { cvt4(W0, g_W0h, i << 2); return; }
    i -= NW04;
    if (i < NW14) { cvt4(W1, g_W1h, i << 2); return; }
    i -= NW14;
    if (i < NW24) { cvt4(W2, g_W2h, i << 2); return; }
    i -= NW24;
    if (i < N_NODES) g_deg[i] = 0;
}

__global__ void count_kernel(const void* __restrict__ ei) {
    int e = blockIdx.x * blockDim.x + threadIdx.x;
    if (e >= NE_TOT) return;
    int is64 = g_is64;
    int dst = (e < N_EDGES) ? edge_at(ei, N_EDGES + e, is64) : (e - N_EDGES);
    atomicAdd(&g_deg[dst], 1);
}

// ---------------------------------------------------------------------------
// Parallel exclusive scan (2 kernels)
// ---------------------------------------------------------------------------
#define SCH 256
#define SNB ((N_NODES + SCH - 1) / SCH)   // 196

__global__ void psum_kernel() {
    int b = blockIdx.x, t = threadIdx.x;
    int i = b * SCH + t;
    int v = (i < N_NODES) ? g_deg[i] : 0;
    __shared__ int ws[8];
    int lane = t & 31, w = t >> 5;
    #pragma unroll
    for (int o = 16; o; o >>= 1) v += __shfl_xor_sync(0xFFFFFFFFu, v, o);
    if (lane == 0) ws[w] = v;
    __syncthreads();
    if (t == 0) {
        int s = 0;
        #pragma unroll
        for (int k = 0; k < 8; k++) s += ws[k];
        g_bsum[b] = s;
    }
}

__global__ void pwrite_kernel() {
    int b = blockIdx.x, t = threadIdx.x;
    __shared__ int ws[8];
    __shared__ int sbase;
    int lane = t & 31, w = t >> 5;

    int pv = (t < b) ? g_bsum[t] : 0;
    int rv = pv;
    #pragma unroll
    for (int o = 16; o; o >>= 1) rv += __shfl_xor_sync(0xFFFFFFFFu, rv, o);
    if (lane == 0) ws[w] = rv;
    __syncthreads();
    if (t == 0) {
        int s = 0;
        #pragma unroll
        for (int k = 0; k < 8; k++) s += ws[k];
        sbase = s;
    }
    __syncthreads();

    int i = b * SCH + t;
    int v = (i < N_NODES) ? g_deg[i] : 0;
    int x = v;
    #pragma unroll
    for (int o = 1; o < 32; o <<= 1) {
        int u = __shfl_up_sync(0xFFFFFFFFu, x, o);
        if (lane >= o) x += u;
    }
    __syncthreads();
    if (lane == 31) ws[w] = x;
    __syncthreads();
    int wbase = 0;
    #pragma unroll
    for (int k = 0; k < 8; k++) if (k < w) wbase += ws[k];
    int excl = sbase + wbase + x - v;
    if (i < N_NODES) {
        g_rowptr[i] = excl;
        g_cursor[i] = excl;
    }
    if (i == N_NODES - 1) g_rowptr[N_NODES] = excl + v;
}

__global__ void fill_kernel(const void* __restrict__ ei) {
    int e = blockIdx.x * blockDim.x + threadIdx.x;
    if (e >= NE_TOT) return;
    int is64 = g_is64;
    int src, dst;
    if (e < N_EDGES) {
        src = edge_at(ei, e, is64);
        dst = edge_at(ei, N_EDGES + e, is64);
    } else {
        src = dst = e - N_EDGES;
    }
    int pos = atomicAdd(&g_cursor[dst], 1);
    if (pos >= 0 && pos < NE_TOT) g_col[pos] = src;
}

// ---------------------------------------------------------------------------
// fp16 HMMA GEMM, 128x128 tile (2 heads), 3-stage cp.async, fused epilogue.
// Used for layer 0 (K=128).
// ---------------------------------------------------------------------------
#define HBM 128
#define HBN 128
#define HBK 32
#define HLA 40
#define HLB 136
#define HST 3
#define STG_LD 72
#define HPOOLB 56832
#define HBS_OFF (HST * HBM * HLA)

template<bool GUARD>
__global__ __launch_bounds__(256) void h_gemm_fused(
    const __half* __restrict__ A, const __half* __restrict__ B,
    int M, int K,
    const float* __restrict__ a_s, const float* __restrict__ a_d,
    float* __restrict__ als, float* __restrict__ ald,
    __half* __restrict__ h16)
{
    __shared__ __align__(16) char pool[HPOOLB];
    __half* Asf = (__half*)pool;
    __half* Bsf = Asf + HBS_OFF;
    float*  stg = (float*)pool;

    const int N = FEAT;
    int tid  = threadIdx.x;
    int warp = tid >> 5;
    int lane = tid & 31;
    int wm   = warp >> 1;
    int wn   = warp & 1;
    int row0 = blockIdx.y * HBM;
    int col0 = blockIdx.x * HBN;

    uint32_t As_a = (uint32_t)__cvta_generic_to_shared(Asf);
    uint32_t Bs_a = (uint32_t)__cvta_generic_to_shared(Bsf);

    wmma::fragment<wmma::accumulator, 16, 16, 16, float> acc[2][4];
    #pragma unroll
    for (int i = 0; i < 2; i++)
        #pragma unroll
        for (int j = 0; j < 4; j++)
            wmma::fill_fragment(acc[i][j], 0.0f);

    const int T = K / HBK;

    auto load_stage = [&](int it) {
        int st = it % HST;
        int k0 = it * HBK;
        {
            int r  = tid >> 1;
            int co = (tid & 1) * 16;
            const __half* gp = A + (size_t)(row0 + r) * K + k0 + co;
            int sb = 16;
            if (GUARD && (row0 + r) >= M) sb = 0;
            uint32_t sa = As_a + (uint32_t)(((st * HBM + r) * HLA + co) * 2);
            cp_async16(sa,      gp,     sb);
            cp_async16(sa + 16, gp + 8, sb);
        }
        {
            int r  = tid >> 3;
            int cq = (tid & 7) * 16;
            const __half* gp = B + (size_t)(k0 + r) * N + col0 + cq;
            uint32_t sa = Bs_a + (uint32_t)(((st * HBK + r) * HLB + cq) * 2);
            cp_async16(sa,      gp,     16);
            cp_async16(sa + 16, gp + 8, 16);
        }
        cp_commit();
    };

    load_stage(0);
    if (T > 1) load_stage(1);
    for (int it = 0; it < T; it++) {
        int cur = it % HST;
        if (it + 2 < T) {
            load_stage(it + 2);
            asm volatile("cp.async.wait_group 2;\n");
        } else if (it + 1 < T) {
            asm volatile("cp.async.wait_group 1;\n");
        } else {
            asm volatile("cp.async.wait_group 0;\n");
        }
        __syncthreads();

        #pragma unroll
        for (int kk = 0; kk < HBK; kk += 16) {
            wmma::fragment<wmma::matrix_a, 16, 16, 16, __half, wmma::row_major> af[2];
            wmma::fragment<wmma::matrix_b, 16, 16, 16, __half, wmma::row_major> bf[4];
            #pragma unroll
            for (int i = 0; i < 2; i++)
                wmma::load_matrix_sync(af[i], Asf + (cur * HBM + wm * 32 + i * 16) * HLA + kk, HLA);
            #pragma unroll
            for (int j = 0; j < 4; j++)
                wmma::load_matrix_sync(bf[j], Bsf + (cur * HBK + kk) * HLB + wn * 64 + j * 16, HLB);
            #pragma unroll
            for (int i = 0; i < 2; i++)
                #pragma unroll
                for (int j = 0; j < 4; j++)
                    wmma::mma_sync(acc[i][j], af[i], bf[j], acc[i][j]);
        }
        __syncthreads();
    }

    #pragma unroll 1
    for (int h = 0; h < 2; h++) {
        if (h == 1) __syncthreads();
        if (wn == h) {
            #pragma unroll
            for (int i = 0; i < 2; i++)
                #pragma unroll
                for (int j = 0; j < 4; j++)
                    wmma::store_matrix_sync(
                        stg + (size_t)(wm * 32 + i * 16) * STG_LD + j * 16,
                        acc[i][j], STG_LD, wmma::mem_row_major);
        }
        __syncthreads();

        int head = (col0 >> 6) + h;
        float as0 = a_s[head * 64 + 2 * lane];
        float as1 = a_s[head * 64 + 2 * lane + 1];
        float ad0 = a_d[head * 64 + 2 * lane];
        float ad1 = a_d[head * 64 + 2 * lane + 1];

        #pragma unroll
        for (int rr = 0; rr < 16; rr++) {
            int r = warp * 16 + rr;
            int grow = row0 + r;
            float2 v = *(const float2*)(stg + (size_t)r * STG_LD + 2 * lane);
            bool ok = (grow < N_NODES);
            if (ok)
                *(__half2*)(h16 + (size_t)grow * FEAT + head * 64 + 2 * lane) =
                    __floats2half2_rn(v.x, v.y);
            float s = fmaf(v.y, as1, v.x * as0);
            float d = fmaf(v.y, ad1, v.x * ad0);
            #pragma unroll
            for (int o = 16; o; o >>= 1) {
                s += __shfl_xor_sync(0xFFFFFFFFu, s, o);
                d += __shfl_xor_sync(0xFFFFFFFFu, d, o);
            }
            if (lane == 0 && ok) {
                als[grow * 8 + head] = s;
                ald[grow * 8 + head] = d;
            }
        }
    }
}

// ---------------------------------------------------------------------------
// fp16 HMMA GEMM, 128x256 tile (4 heads), 512 threads, for layer 1 (K=512).
// Halves A-matrix re-reads vs 128x128 (2 column blocks instead of 4).
// ---------------------------------------------------------------------------
#define WBM 128
#define WBN 256
#define WBK 32
#define WLA 40      // halfs per As row
#define WLB 264     // halfs per Bs row
#define WST 3
// bytes: As = 3*128*40*2 = 30720, Bs = 3*32*264*2 = 50688 -> 81408
#define WPOOLB 81408
#define WBS_OFF (WST * WBM * WLA)

__global__ __launch_bounds__(512) void h_gemm_wide_fused(
    const __half* __restrict__ A, const __half* __restrict__ B,
    int K,
    const float* __restrict__ a_s, const float* __restrict__ a_d,
    float* __restrict__ als, float* __restrict__ ald,
    __half* __restrict__ h16)
{
    __shared__ __align__(16) char pool[WPOOLB];
    __half* Asf = (__half*)pool;
    __half* Bsf = Asf + WBS_OFF;
    float*  stg = (float*)pool;     // [128][STG_LD] epilogue stage

    const int N = FEAT;
    int tid  = threadIdx.x;
    int warp = tid >> 5;
    int lane = tid & 31;
    int wm   = warp >> 2;      // 0..3
    int wn   = warp & 3;       // 0..3
    int row0 = blockIdx.y * WBM;
    int col0 = blockIdx.x * WBN;

    uint32_t As_a = (uint32_t)__cvta_generic_to_shared(Asf);
    uint32_t Bs_a = (uint32_t)__cvta_generic_to_shared(Bsf);

    wmma::fragment<wmma::accumulator, 16, 16, 16, float> acc[2][4];
    #pragma unroll
    for (int i = 0; i < 2; i++)
        #pragma unroll
        for (int j = 0; j < 4; j++)
            wmma::fill_fragment(acc[i][j], 0.0f);

    const int T = K / WBK;

    auto load_stage = [&](int it) {
        int st = it % WST;
        int k0 = it * WBK;
        {   // A: 128 rows x 32 halfs (64B/row); 4 threads/row x 16B
            int r  = tid >> 2;
            int co = (tid & 3) * 8;
            const __half* gp = A + (size_t)(row0 + r) * K + k0 + co;
            uint32_t sa = As_a + (uint32_t)(((st * WBM + r) * WLA + co) * 2);
            cp_async16(sa, gp, 16);
        }
        {   // B: 32 rows x 256 halfs (512B/row); 16 threads/row x 32B
            int r  = tid >> 4;
            int cq = (tid & 15) * 16;
            const __half* gp = B + (size_t)(k0 + r) * N + col0 + cq;
            uint32_t sa = Bs_a + (uint32_t)(((st * WBK + r) * WLB + cq) * 2);
            cp_async16(sa,      gp,     16);
            cp_async16(sa + 16, gp + 8, 16);
        }
        cp_commit();
    };

    load_stage(0);
    if (T > 1) load_stage(1);
    for (int it = 0; it < T; it++) {
        int cur = it % WST;
        if (it + 2 < T) {
            load_stage(it + 2);
            asm volatile("cp.async.wait_group 2;\n");
        } else if (it + 1 < T) {
            asm volatile("cp.async.wait_group 1;\n");
        } else {
            asm volatile("cp.async.wait_group 0;\n");
        }
        __syncthreads();

        #pragma unroll
        for (int kk = 0; kk < WBK; kk += 16) {
            wmma::fragment<wmma::matrix_a, 16, 16, 16, __half, wmma::row_major> af[2];
            wmma::fragment<wmma::matrix_b, 16, 16, 16, __half, wmma::row_major> bf[4];
            #pragma unroll
            for (int i = 0; i < 2; i++)
                wmma::load_matrix_sync(af[i], Asf + (cur * WBM + wm * 32 + i * 16) * WLA + kk, WLA);
            #pragma unroll
            for (int j = 0; j < 4; j++)
                wmma::load_matrix_sync(bf[j], Bsf + (cur * WBK + kk) * WLB + wn * 64 + j * 16, WLB);
            #pragma unroll
            for (int i = 0; i < 2; i++)
                #pragma unroll
                for (int j = 0; j < 4; j++)
                    wmma::mma_sync(acc[i][j], af[i], bf[j], acc[i][j]);
        }
        __syncthreads();
    }

    // ---- Epilogue: 4 chunks of 64 cols (one head each) via smem ----
    #pragma unroll 1
    for (int h = 0; h < 4; h++) {
        if (h > 0) __syncthreads();
        if (wn == h) {
            #pragma unroll
            for (int i = 0; i < 2; i++)
                #pragma unroll
                for (int j = 0; j < 4; j++)
                    wmma::store_matrix_sync(
                        stg + (size_t)(wm * 32 + i * 16) * STG_LD + j * 16,
                        acc[i][j], STG_LD, wmma::mem_row_major);
        }
        __syncthreads();

        int head = (col0 >> 6) + h;
        float as0 = a_s[head * 64 + 2 * lane];
        float as1 = a_s[head * 64 + 2 * lane + 1];
        float ad0 = a_d[head * 64 + 2 * lane];
        float ad1 = a_d[head * 64 + 2 * lane + 1];

        // 16 warps x 8 rows = 128 rows; lane covers cols 2l, 2l+1
        #pragma unroll
        for (int rr = 0; rr < 8; rr++) {
            int r = warp * 8 + rr;
            int grow = row0 + r;
            float2 v = *(const float2*)(stg + (size_t)r * STG_LD + 2 * lane);
            bool ok = (grow < N_NODES);
            if (ok)
                *(__half2*)(h16 + (size_t)grow * FEAT + head * 64 + 2 * lane) =
                    __floats2half2_rn(v.x, v.y);
            float s = fmaf(v.y, as1, v.x * as0);
            float d = fmaf(v.y, ad1, v.x * ad0);
            #pragma unroll
            for (int o = 16; o; o >>= 1) {
                s += __shfl_xor_sync(0xFFFFFFFFu, s, o);
                d += __shfl_xor_sync(0xFFFFFFFFu, d, o);
            }
            if (lane == 0 && ok) {
                als[grow * 8 + head] = s;
                ald[grow * 8 + head] = d;
            }
        }
    }
}

// ---------------------------------------------------------------------------
// Layer-2 fp16 GEMM + fused al2 epilogue.
// ---------------------------------------------------------------------------
__global__ __launch_bounds__(256) void h_gemm16_fused(
    const __half* __restrict__ A, const __half* __restrict__ B,
    float* __restrict__ H2,
    const float* __restrict__ a_s, const float* __restrict__ a_d,
    float* __restrict__ als, float* __restrict__ ald)
{
    __shared__ __align__(16) __half As[128][40];
    __shared__ __align__(16) __half Bs[32][24];
    __shared__ __align__(16) float  stg[128][20];
    int tid  = threadIdx.x;
    int warp = tid >> 5;
    int row0 = blockIdx.x * 128;

    wmma::fragment<wmma::accumulator, 16, 16, 16, float> acc;
    wmma::fill_fragment(acc, 0.0f);

    for (int k0 = 0; k0 < FEAT; k0 += 32) {
        {
            int r  = tid >> 1;
            int co = (tid & 1) * 16;
            const __half* gp = A + (size_t)(row0 + r) * FEAT + k0 + co;
            *(uint4*)(&As[r][co])     = *(const uint4*)(gp);
            *(uint4*)(&As[r][co + 8]) = *(const uint4*)(gp + 8);
        }
        if (tid < 64) {
            int r  = tid >> 1;
            int co = (tid & 1) * 8;
            *(uint4*)(&Bs[r][co]) = *(const uint4*)(B + (size_t)(k0 + r) * 16 + co);
        }
        __syncthreads();
        #pragma unroll
        for (int kk = 0; kk < 32; kk += 16) {
            wmma::fragment<wmma::matrix_a, 16, 16, 16, __half, wmma::row_major> af;
            wmma::fragment<wmma::matrix_b, 16, 16, 16, __half, wmma::row_major> bf;
            wmma::load_matrix_sync(af, &As[warp * 16][kk], 40);
            wmma::load_matrix_sync(bf, &Bs[kk][0], 24);
            wmma::mma_sync(acc, af, bf, acc);
        }
        __syncthreads();
    }

    wmma::store_matrix_sync(&stg[warp * 16][0], acc, 20, wmma::mem_row_major);
    __syncthreads();

    if (tid < 128) {
        int grow = row0 + tid;
        if (grow < N_NODES) {
            float s = 0.f, d = 0.f;
            float* dst = H2 + (size_t)grow * 16;
            #pragma unroll
            for (int c = 0; c < 16; c += 4) {
                float4 v = *(const float4*)(&stg[tid][c]);
                *(float4*)(dst + c) = v;
                s = fmaf(v.x, a_s[c+0], s); d = fmaf(v.x, a_d[c+0], d);
                s = fmaf(v.y, a_s[c+1], s); d = fmaf(v.y, a_d[c+1], d);
                s = fmaf(v.z, a_s[c+2], s); d = fmaf(v.z, a_d[c+2], d);
                s = fmaf(v.w, a_s[c+3], s); d = fmaf(v.w, a_d[c+3], d);
            }
            als[grow] = s;
            ald[grow] = d;
        }
    }
}

// ---------------------------------------------------------------------------
// Softmax + aggregation (H=8, C=64): fp16 gather, self-shifted softmax,
// ELU fused, fp16 output.
// ---------------------------------------------------------------------------
__global__ __launch_bounds__(128) void agg_kernel(
    const __half* __restrict__ h16, const float* __restrict__ als,
    const float* __restrict__ ald, const float* __restrict__ bias,
    __half* __restrict__ out)
{
    int n = blockIdx.x;
    int t = threadIdx.x;
    int hd = t >> 4;
    int c4 = (t & 15) << 2;
    int start = g_rowptr[n], end = g_rowptr[n + 1];

    float adv = ald[n * 8 + hd];
    float shift = lrelu(als[n * 8 + hd] + adv);

    float4 acc = make_float4(0.f, 0.f, 0.f, 0.f);
    float den = 0.f;
    for (int i = start; i < end; i++) {
        int s = g_col[i];
        float w = __expf(lrelu(als[s * 8 + hd] + adv) - shift);
        den += w;
        uint2 u = *(const uint2*)(h16 + (size_t)s * FEAT + hd * 64 + c4);
        float2 f0 = __half22float2(*reinterpret_cast<__half2*>(&u.x));
        float2 f1 = __half22float2(*reinterpret_cast<__half2*>(&u.y));
        acc.x = fmaf(w, f0.x, acc.x);
        acc.y = fmaf(w, f0.y, acc.y);
        acc.z = fmaf(w, f1.x, acc.z);
        acc.w = fmaf(w, f1.y, acc.w);
    }
    float inv = 1.f / den;
    int c = hd * 64 + c4;
    float r0 = eluf(acc.x * inv + bias[c + 0]);
    float r1 = eluf(acc.y * inv + bias[c + 1]);
    float r2 = eluf(acc.z * inv + bias[c + 2]);
    float r3 = eluf(acc.w * inv + bias[c + 3]);
    __half* op = out + (size_t)n * FEAT + c;
    *(__half2*)(op)     = __floats2half2_rn(r0, r1);
    *(__half2*)(op + 2) = __floats2half2_rn(r2, r3);
}

// Final aggregation (H=1, C=16). One warp per node, fp32 h2.
__global__ __launch_bounds__(128) void agg_final_kernel(
    const float* __restrict__ h2, const float* __restrict__ als,
    const float* __restrict__ ald, const float* __restrict__ bias,
    float* __restrict__ out)
{
    int wid = (blockIdx.x * blockDim.x + threadIdx.x) >> 5;
    int lane = threadIdx.x & 31;
    if (wid >= N_NODES) return;
    int n = wid;
    int start = g_rowptr[n], end = g_rowptr[n + 1];
    float adv = ald[n];
    float shift = lrelu(als[n] + adv);
    float acc = 0.f, den = 0.f;
    for (int i = start; i < end; i++) {
        int s = g_col[i];
        float w = __expf(lrelu(als[s] + adv) - shift);
        den += w;
        if (lane < 16) acc = fmaf(w, h2[(size_t)s * 16 + lane], acc);
    }
    if (lane < 16) out[(size_t)n * 16 + lane] = acc / den + bias[lane];
}

// ---------------------------------------------------------------------------
// Launch
// ---------------------------------------------------------------------------
extern "C" void kernel_launch(void* const* d_in, const int* in_sizes, int n_in,
                              void* d_out, int out_size)
{
    const float* x    = (const float*)d_in[0];
    const void*  ei   = d_in[1];
    const float* W0   = (const float*)d_in[2];
    const float* a_s0 = (const float*)d_in[3];
    const float* a_d0 = (const float*)d_in[4];
    const float* b0   = (const float*)d_in[5];
    const float* W1   = (const float*)d_in[6];
    const float* a_s1 = (const float*)d_in[7];
    const float* a_d1 = (const float*)d_in[8];
    const float* b1   = (const float*)d_in[9];
    const float* W2   = (const float*)d_in[10];
    const float* a_s2 = (const float*)d_in[11];
    const float* a_d2 = (const float*)d_in[12];
    const float* b2   = (const float*)d_in[13];
    float*       out  = (float*)d_out;

    float *H2, *ALS, *ALD;
    __half *X16, *O16, *H16, *W0H, *W1H, *W2H;
    cudaGetSymbolAddress((void**)&X16, g_x16);
    cudaGetSymbolAddress((void**)&O16, g_O16);
    cudaGetSymbolAddress((void**)&H16, g_h16);
    cudaGetSymbolAddress((void**)&W0H, g_W0h);
    cudaGetSymbolAddress((void**)&W1H, g_W1h);
    cudaGetSymbolAddress((void**)&W2H, g_W2h);
    cudaGetSymbolAddress((void**)&H2,  g_H2);
    cudaGetSymbolAddress((void**)&ALS, g_als);
    cudaGetSymbolAddress((void**)&ALD, g_ald);

    // --- setup + CSR: exactly 5 launches so gemm0 is launch #6 (ncu -s 5) ---
    setup_kernel<<<(NSET + 255) / 256, 256>>>(x, W0, W1, W2, (const int*)ei);
    count_kernel<<<(NE_TOT + 255) / 256, 256>>>(ei);
    psum_kernel<<<SNB, SCH>>>();
    pwrite_kernel<<<SNB, SCH>>>();
    fill_kernel<<<(NE_TOT + 255) / 256, 256>>>(ei);

    // --- Layer 0: 128x128 tiles (K=128) ---
    dim3 gg0(FEAT / HBN, M_PAD / HBM);   // (4, 391)
    h_gemm_fused<true><<<gg0, 256>>>(X16, W0H, N_NODES, F_IN,
                                     a_s0, a_d0, ALS, ALD, H16);
    agg_kernel<<<N_NODES, 128>>>(H16, ALS, ALD, b0, O16);

    // --- Layer 1: 128x256 tiles (K=512), halved A re-reads ---
    dim3 gg1(FEAT / WBN, M_PAD / WBM);   // (2, 391)
    h_gemm_wide_fused<<<gg1, 512>>>(O16, W1H, FEAT,
                                    a_s1, a_d1, ALS, ALD, H16);
    agg_kernel<<<N_NODES, 128>>>(H16, ALS, ALD, b1, O16);

    // --- Layer 2 ---
    h_gemm16_fused<<<M_PAD / 128, 256>>>(O16, W2H, H2, a_s2, a_d2, ALS, ALD);
    agg_final_kernel<<<(N_NODES * 32 + 127) / 128, 128>>>(H2, ALS, ALD, b2, out);
}

// round 10
// speedup vs baseline: 1.0134x; 1.0134x over previous
#include <cuda_runtime.h>
#include <cuda_bf16.h>
#include <cuda_fp16.h>
#include <mma.h>
#include <math.h>
#include <stdint.h>

using namespace nvcuda;

#define N_NODES 50000
#define M_PAD   50048
#define N_EDGES 400000
#define NE_TOT  (N_EDGES + N_NODES)
#define F_IN    128
#define HID     64
#define HEADS   8
#define FEAT    (HEADS * HID)          // 512
#define N_CLASSES 16
#define NEG_SLOPE 0.2f

// ---------------------------------------------------------------------------
// Static scratch
// ---------------------------------------------------------------------------
__device__ __half g_x16 [(size_t)M_PAD * F_IN];
__device__ __half g_O16 [(size_t)M_PAD * FEAT];
__device__ __half g_h16 [(size_t)M_PAD * FEAT];
__device__ __half g_W0h [F_IN * FEAT];
__device__ __half g_W1h [FEAT * FEAT];
__device__ __half g_W2h [FEAT * N_CLASSES];
__device__ float  g_H2  [(size_t)M_PAD * N_CLASSES];
__device__ float  g_als [(size_t)N_NODES * HEADS];
__device__ float  g_ald [(size_t)N_NODES * HEADS];
__device__ int    g_deg   [N_NODES];
__device__ int    g_rowptr[N_NODES + 1];
__device__ int    g_cursor[N_NODES];
__device__ int    g_col   [NE_TOT];
__device__ int    g_bsum  [256];
__device__ int    g_is64;

__device__ __forceinline__ float eluf(float x)   { return x > 0.f ? x : expm1f(x); }
__device__ __forceinline__ float lrelu(float x)  { return x > 0.f ? x : NEG_SLOPE * x; }
__device__ __forceinline__ int clampi(int v) {
    return (v < 0) ? 0 : (v >= N_NODES ? N_NODES - 1 : v);
}
__device__ __forceinline__ int edge_at(const void* ei, int idx, int is64) {
    if (is64) return clampi((int)((const long long*)ei)[idx]);
    return clampi(((const int*)ei)[idx]);
}

__device__ __forceinline__ void cp_async16(uint32_t saddr, const void* gptr, int src_bytes) {
    asm volatile("cp.async.cg.shared.global [%0], [%1], 16, %2;\n"
                 :: "r"(saddr), "l"(gptr), "r"(src_bytes));
}
__device__ __forceinline__ void cp_commit() {
    asm volatile("cp.async.commit_group;\n");
}

// ---------------------------------------------------------------------------
// Setup kernel: fp16 conversions (x, W0, W1, W2) + deg zeroing + dtype probe.
// ---------------------------------------------------------------------------
#define NX4  (N_NODES * F_IN / 4)
#define NW04 (F_IN * FEAT / 4)
#define NW14 (FEAT * FEAT / 4)
#define NW24 (FEAT * N_CLASSES / 4)
#define NSET (NX4 + NW04 + NW14 + NW24 + N_NODES)

__device__ __forceinline__ void cvt4(const float* s, __half* d, int i4) {
    float4 v = *(const float4*)(s + i4);
    *(__half2*)(d + i4)     = __floats2half2_rn(v.x, v.y);
    *(__half2*)(d + i4 + 2) = __floats2half2_rn(v.z, v.w);
}

__global__ void setup_kernel(const float* __restrict__ x,
                             const float* __restrict__ W0,
                             const float* __restrict__ W1,
                             const float* __restrict__ W2,
                             const int* __restrict__ ei_raw)
{
    int i = blockIdx.x * blockDim.x + threadIdx.x;
    if (i == 0) {
        int any_nonzero = 0;
        #pragma unroll 1
        for (int k = 0; k < 64; k++) any_nonzero |= ei_raw[2 * k + 1];
        g_is64 = (any_nonzero == 0) ? 1 : 0;
    }
    if (i < NX4) { cvt4(x, g_x16, i << 2); return; }
    i -= NX4;
    if (i < NW04) { cvt4(W0, g_W0h, i << 2); return; }
    i -= NW04;
    if (i < NW14) { cvt4(W1, g_W1h, i << 2); return; }
    i -= NW14;
    if (i < NW24) { cvt4(W2, g_W2h, i << 2); return; }
    i -= NW24;
    if (i < N_NODES) g_deg[i] = 0;
}

__global__ void count_kernel(const void* __restrict__ ei) {
    int e = blockIdx.x * blockDim.x + threadIdx.x;
    if (e >= NE_TOT) return;
    int is64 = g_is64;
    int dst = (e < N_EDGES) ? edge_at(ei, N_EDGES + e, is64) : (e - N_EDGES);
    atomicAdd(&g_deg[dst], 1);
}

// ---------------------------------------------------------------------------
// Parallel exclusive scan (2 kernels)
// ---------------------------------------------------------------------------
#define SCH 256
#define SNB ((N_NODES + SCH - 1) / SCH)   // 196

__global__ void psum_kernel() {
    int b = blockIdx.x, t = threadIdx.x;
    int i = b * SCH + t;
    int v = (i < N_NODES) ? g_deg[i] : 0;
    __shared__ int ws[8];
    int lane = t & 31, w = t >> 5;
    #pragma unroll
    for (int o = 16; o; o >>= 1) v += __shfl_xor_sync(0xFFFFFFFFu, v, o);
    if (lane == 0) ws[w] = v;
    __syncthreads();
    if (t == 0) {
        int s = 0;
        #pragma unroll
        for (int k = 0; k < 8; k++) s += ws[k];
        g_bsum[b] = s;
    }
}

__global__ void pwrite_kernel() {
    int b = blockIdx.x, t = threadIdx.x;
    __shared__ int ws[8];
    __shared__ int sbase;
    int lane = t & 31, w = t >> 5;

    int pv = (t < b) ? g_bsum[t] : 0;
    int rv = pv;
    #pragma unroll
    for (int o = 16; o; o >>= 1) rv += __shfl_xor_sync(0xFFFFFFFFu, rv, o);
    if (lane == 0) ws[w] = rv;
    __syncthreads();
    if (t == 0) {
        int s = 0;
        #pragma unroll
        for (int k = 0; k < 8; k++) s += ws[k];
        sbase = s;
    }
    __syncthreads();

    int i = b * SCH + t;
    int v = (i < N_NODES) ? g_deg[i] : 0;
    int x = v;
    #pragma unroll
    for (int o = 1; o < 32; o <<= 1) {
        int u = __shfl_up_sync(0xFFFFFFFFu, x, o);
        if (lane >= o) x += u;
    }
    __syncthreads();
    if (lane == 31) ws[w] = x;
    __syncthreads();
    int wbase = 0;
    #pragma unroll
    for (int k = 0; k < 8; k++) if (k < w) wbase += ws[k];
    int excl = sbase + wbase + x - v;
    if (i < N_NODES) {
        g_rowptr[i] = excl;
        g_cursor[i] = excl;
    }
    if (i == N_NODES - 1) g_rowptr[N_NODES] = excl + v;
}

__global__ void fill_kernel(const void* __restrict__ ei) {
    int e = blockIdx.x * blockDim.x + threadIdx.x;
    if (e >= NE_TOT) return;
    int is64 = g_is64;
    int src, dst;
    if (e < N_EDGES) {
        src = edge_at(ei, e, is64);
        dst = edge_at(ei, N_EDGES + e, is64);
    } else {
        src = dst = e - N_EDGES;
    }
    int pos = atomicAdd(&g_cursor[dst], 1);
    if (pos >= 0 && pos < NE_TOT) g_col[pos] = src;
}

// ---------------------------------------------------------------------------
// fp16 HMMA GEMM, 128x128 tile (2 heads), 3-stage cp.async, fused epilogue.
// (round-8 proven config; used for BOTH big layers)
// ---------------------------------------------------------------------------
#define HBM 128
#define HBN 128
#define HBK 32
#define HLA 40
#define HLB 136
#define HST 3
#define STG_LD 72
#define HPOOLB 56832
#define HBS_OFF (HST * HBM * HLA)

template<bool GUARD>
__global__ __launch_bounds__(256) void h_gemm_fused(
    const __half* __restrict__ A, const __half* __restrict__ B,
    int M, int K,
    const float* __restrict__ a_s, const float* __restrict__ a_d,
    float* __restrict__ als, float* __restrict__ ald,
    __half* __restrict__ h16)
{
    __shared__ __align__(16) char pool[HPOOLB];
    __half* Asf = (__half*)pool;
    __half* Bsf = Asf + HBS_OFF;
    float*  stg = (float*)pool;

    const int N = FEAT;
    int tid  = threadIdx.x;
    int warp = tid >> 5;
    int lane = tid & 31;
    int wm   = warp >> 1;
    int wn   = warp & 1;
    int row0 = blockIdx.y * HBM;
    int col0 = blockIdx.x * HBN;

    uint32_t As_a = (uint32_t)__cvta_generic_to_shared(Asf);
    uint32_t Bs_a = (uint32_t)__cvta_generic_to_shared(Bsf);

    wmma::fragment<wmma::accumulator, 16, 16, 16, float> acc[2][4];
    #pragma unroll
    for (int i = 0; i < 2; i++)
        #pragma unroll
        for (int j = 0; j < 4; j++)
            wmma::fill_fragment(acc[i][j], 0.0f);

    const int T = K / HBK;

    auto load_stage = [&](int it) {
        int st = it % HST;
        int k0 = it * HBK;
        {
            int r  = tid >> 1;
            int co = (tid & 1) * 16;
            const __half* gp = A + (size_t)(row0 + r) * K + k0 + co;
            int sb = 16;
            if (GUARD && (row0 + r) >= M) sb = 0;
            uint32_t sa = As_a + (uint32_t)(((st * HBM + r) * HLA + co) * 2);
            cp_async16(sa,      gp,     sb);
            cp_async16(sa + 16, gp + 8, sb);
        }
        {
            int r  = tid >> 3;
            int cq = (tid & 7) * 16;
            const __half* gp = B + (size_t)(k0 + r) * N + col0 + cq;
            uint32_t sa = Bs_a + (uint32_t)(((st * HBK + r) * HLB + cq) * 2);
            cp_async16(sa,      gp,     16);
            cp_async16(sa + 16, gp + 8, 16);
        }
        cp_commit();
    };

    load_stage(0);
    if (T > 1) load_stage(1);
    for (int it = 0; it < T; it++) {
        int cur = it % HST;
        if (it + 2 < T) {
            load_stage(it + 2);
            asm volatile("cp.async.wait_group 2;\n");
        } else if (it + 1 < T) {
            asm volatile("cp.async.wait_group 1;\n");
        } else {
            asm volatile("cp.async.wait_group 0;\n");
        }
        __syncthreads();

        #pragma unroll
        for (int kk = 0; kk < HBK; kk += 16) {
            wmma::fragment<wmma::matrix_a, 16, 16, 16, __half, wmma::row_major> af[2];
            wmma::fragment<wmma::matrix_b, 16, 16, 16, __half, wmma::row_major> bf[4];
            #pragma unroll
            for (int i = 0; i < 2; i++)
                wmma::load_matrix_sync(af[i], Asf + (cur * HBM + wm * 32 + i * 16) * HLA + kk, HLA);
            #pragma unroll
            for (int j = 0; j < 4; j++)
                wmma::load_matrix_sync(bf[j], Bsf + (cur * HBK + kk) * HLB + wn * 64 + j * 16, HLB);
            #pragma unroll
            for (int i = 0; i < 2; i++)
                #pragma unroll
                for (int j = 0; j < 4; j++)
                    wmma::mma_sync(acc[i][j], af[i], bf[j], acc[i][j]);
        }
        __syncthreads();
    }

    #pragma unroll 1
    for (int h = 0; h < 2; h++) {
        if (h == 1) __syncthreads();
        if (wn == h) {
            #pragma unroll
            for (int i = 0; i < 2; i++)
                #pragma unroll
                for (int j = 0; j < 4; j++)
                    wmma::store_matrix_sync(
                        stg + (size_t)(wm * 32 + i * 16) * STG_LD + j * 16,
                        acc[i][j], STG_LD, wmma::mem_row_major);
        }
        __syncthreads();

        int head = (col0 >> 6) + h;
        float as0 = a_s[head * 64 + 2 * lane];
        float as1 = a_s[head * 64 + 2 * lane + 1];
        float ad0 = a_d[head * 64 + 2 * lane];
        float ad1 = a_d[head * 64 + 2 * lane + 1];

        #pragma unroll
        for (int rr = 0; rr < 16; rr++) {
            int r = warp * 16 + rr;
            int grow = row0 + r;
            float2 v = *(const float2*)(stg + (size_t)r * STG_LD + 2 * lane);
            bool ok = (grow < N_NODES);
            if (ok)
                *(__half2*)(h16 + (size_t)grow * FEAT + head * 64 + 2 * lane) =
                    __floats2half2_rn(v.x, v.y);
            float s = fmaf(v.y, as1, v.x * as0);
            float d = fmaf(v.y, ad1, v.x * ad0);
            #pragma unroll
            for (int o = 16; o; o >>= 1) {
                s += __shfl_xor_sync(0xFFFFFFFFu, s, o);
                d += __shfl_xor_sync(0xFFFFFFFFu, d, o);
            }
            if (lane == 0 && ok) {
                als[grow * 8 + head] = s;
                ald[grow * 8 + head] = d;
            }
        }
    }
}

// ---------------------------------------------------------------------------
// Layer-2 fp16 GEMM + fused al2 epilogue.
// ---------------------------------------------------------------------------
__global__ __launch_bounds__(256) void h_gemm16_fused(
    const __half* __restrict__ A, const __half* __restrict__ B,
    float* __restrict__ H2,
    const float* __restrict__ a_s, const float* __restrict__ a_d,
    float* __restrict__ als, float* __restrict__ ald)
{
    __shared__ __align__(16) __half As[128][40];
    __shared__ __align__(16) __half Bs[32][24];
    __shared__ __align__(16) float  stg[128][20];
    int tid  = threadIdx.x;
    int warp = tid >> 5;
    int row0 = blockIdx.x * 128;

    wmma::fragment<wmma::accumulator, 16, 16, 16, float> acc;
    wmma::fill_fragment(acc, 0.0f);

    for (int k0 = 0; k0 < FEAT; k0 += 32) {
        {
            int r  = tid >> 1;
            int co = (tid & 1) * 16;
            const __half* gp = A + (size_t)(row0 + r) * FEAT + k0 + co;
            *(uint4*)(&As[r][co])     = *(const uint4*)(gp);
            *(uint4*)(&As[r][co + 8]) = *(const uint4*)(gp + 8);
        }
        if (tid < 64) {
            int r  = tid >> 1;
            int co = (tid & 1) * 8;
            *(uint4*)(&Bs[r][co]) = *(const uint4*)(B + (size_t)(k0 + r) * 16 + co);
        }
        __syncthreads();
        #pragma unroll
        for (int kk = 0; kk < 32; kk += 16) {
            wmma::fragment<wmma::matrix_a, 16, 16, 16, __half, wmma::row_major> af;
            wmma::fragment<wmma::matrix_b, 16, 16, 16, __half, wmma::row_major> bf;
            wmma::load_matrix_sync(af, &As[warp * 16][kk], 40);
            wmma::load_matrix_sync(bf, &Bs[kk][0], 24);
            wmma::mma_sync(acc, af, bf, acc);
        }
        __syncthreads();
    }

    wmma::store_matrix_sync(&stg[warp * 16][0], acc, 20, wmma::mem_row_major);
    __syncthreads();

    if (tid < 128) {
        int grow = row0 + tid;
        if (grow < N_NODES) {
            float s = 0.f, d = 0.f;
            float* dst = H2 + (size_t)grow * 16;
            #pragma unroll
            for (int c = 0; c < 16; c += 4) {
                float4 v = *(const float4*)(&stg[tid][c]);
                *(float4*)(dst + c) = v;
                s = fmaf(v.x, a_s[c+0], s); d = fmaf(v.x, a_d[c+0], d);
                s = fmaf(v.y, a_s[c+1], s); d = fmaf(v.y, a_d[c+1], d);
                s = fmaf(v.z, a_s[c+2], s); d = fmaf(v.z, a_d[c+2], d);
                s = fmaf(v.w, a_s[c+3], s); d = fmaf(v.w, a_d[c+3], d);
            }
            als[grow] = s;
            ald[grow] = d;
        }
    }
}

// ---------------------------------------------------------------------------
// Softmax + aggregation (H=8, C=64): fp16 gather, self-shifted softmax,
// ELU fused, fp16 output.  Index/logit loads software-pipelined one edge
// ahead to break the 2-deep dependent-load chain.
// ---------------------------------------------------------------------------
__global__ __launch_bounds__(128) void agg_kernel(
    const __half* __restrict__ h16, const float* __restrict__ als,
    const float* __restrict__ ald, const float* __restrict__ bias,
    __half* __restrict__ out)
{
    int n = blockIdx.x;
    int t = threadIdx.x;
    int hd = t >> 4;
    int c4 = (t & 15) << 2;
    int start = g_rowptr[n], end = g_rowptr[n + 1];

    float adv = ald[n * 8 + hd];
    float shift = lrelu(als[n * 8 + hd] + adv);

    float4 acc = make_float4(0.f, 0.f, 0.f, 0.f);
    float den = 0.f;

    int   s_cur  = g_col[start];           // deg >= 1 always (self loop)
    float al_cur = als[s_cur * 8 + hd];
    for (int i = start; i < end; i++) {
        int   s  = s_cur;
        float al = al_cur;
        if (i + 1 < end) {
            s_cur  = g_col[i + 1];
            al_cur = als[s_cur * 8 + hd];
        }
        float w = __expf(lrelu(al + adv) - shift);
        den += w;
        uint2 u = *(const uint2*)(h16 + (size_t)s * FEAT + hd * 64 + c4);
        float2 f0 = __half22float2(*reinterpret_cast<__half2*>(&u.x));
        float2 f1 = __half22float2(*reinterpret_cast<__half2*>(&u.y));
        acc.x = fmaf(w, f0.x, acc.x);
        acc.y = fmaf(w, f0.y, acc.y);
        acc.z = fmaf(w, f1.x, acc.z);
        acc.w = fmaf(w, f1.y, acc.w);
    }
    float inv = 1.f / den;
    int c = hd * 64 + c4;
    float r0 = eluf(acc.x * inv + bias[c + 0]);
    float r1 = eluf(acc.y * inv + bias[c + 1]);
    float r2 = eluf(acc.z * inv + bias[c + 2]);
    float r3 = eluf(acc.w * inv + bias[c + 3]);
    __half* op = out + (size_t)n * FEAT + c;
    *(__half2*)(op)     = __floats2half2_rn(r0, r1);
    *(__half2*)(op + 2) = __floats2half2_rn(r2, r3);
}

// Final aggregation (H=1, C=16). One warp per node, prefetched chain.
__global__ __launch_bounds__(128) void agg_final_kernel(
    const float* __restrict__ h2, const float* __restrict__ als,
    const float* __restrict__ ald, const float* __restrict__ bias,
    float* __restrict__ out)
{
    int wid = (blockIdx.x * blockDim.x + threadIdx.x) >> 5;
    int lane = threadIdx.x & 31;
    if (wid >= N_NODES) return;
    int n = wid;
    int start = g_rowptr[n], end = g_rowptr[n + 1];
    float adv = ald[n];
    float shift = lrelu(als[n] + adv);
    float acc = 0.f, den = 0.f;

    int   s_cur  = g_col[start];
    float al_cur = als[s_cur];
    for (int i = start; i < end; i++) {
        int   s  = s_cur;
        float al = al_cur;
        if (i + 1 < end) {
            s_cur  = g_col[i + 1];
            al_cur = als[s_cur];
        }
        float w = __expf(lrelu(al + adv) - shift);
        den += w;
        if (lane < 16) acc = fmaf(w, h2[(size_t)s * 16 + lane], acc);
    }
    if (lane < 16) out[(size_t)n * 16 + lane] = acc / den + bias[lane];
}

// ---------------------------------------------------------------------------
// Launch
// ---------------------------------------------------------------------------
extern "C" void kernel_launch(void* const* d_in, const int* in_sizes, int n_in,
                              void* d_out, int out_size)
{
    const float* x    = (const float*)d_in[0];
    const void*  ei   = d_in[1];
    const float* W0   = (const float*)d_in[2];
    const float* a_s0 = (const float*)d_in[3];
    const float* a_d0 = (const float*)d_in[4];
    const float* b0   = (const float*)d_in[5];
    const float* W1   = (const float*)d_in[6];
    const float* a_s1 = (const float*)d_in[7];
    const float* a_d1 = (const float*)d_in[8];
    const float* b1   = (const float*)d_in[9];
    const float* W2   = (const float*)d_in[10];
    const float* a_s2 = (const float*)d_in[11];
    const float* a_d2 = (const float*)d_in[12];
    const float* b2   = (const float*)d_in[13];
    float*       out  = (float*)d_out;

    float *H2, *ALS, *ALD;
    __half *X16, *O16, *H16, *W0H, *W1H, *W2H;
    cudaGetSymbolAddress((void**)&X16, g_x16);
    cudaGetSymbolAddress((void**)&O16, g_O16);
    cudaGetSymbolAddress((void**)&H16, g_h16);
    cudaGetSymbolAddress((void**)&W0H, g_W0h);
    cudaGetSymbolAddress((void**)&W1H, g_W1h);
    cudaGetSymbolAddress((void**)&W2H, g_W2h);
    cudaGetSymbolAddress((void**)&H2,  g_H2);
    cudaGetSymbolAddress((void**)&ALS, g_als);
    cudaGetSymbolAddress((void**)&ALD, g_ald);

    // --- setup + CSR ---
    setup_kernel<<<(NSET + 255) / 256, 256>>>(x, W0, W1, W2, (const int*)ei);
    count_kernel<<<(NE_TOT + 255) / 256, 256>>>(ei);
    psum_kernel<<<SNB, SCH>>>();
    pwrite_kernel<<<SNB, SCH>>>();
    fill_kernel<<<(NE_TOT + 255) / 256, 256>>>(ei);

    dim3 gg(FEAT / HBN, M_PAD / HBM);   // (4, 391)

    // --- Layer 0 (K=128) ---
    h_gemm_fused<true><<<gg, 256>>>(X16, W0H, N_NODES, F_IN,
                                    a_s0, a_d0, ALS, ALD, H16);
    agg_kernel<<<N_NODES, 128>>>(H16, ALS, ALD, b0, O16);

    // --- Layer 1 (K=512) ---
    h_gemm_fused<false><<<gg, 256>>>(O16, W1H, M_PAD, FEAT,
                                     a_s1, a_d1, ALS, ALD, H16);
    agg_kernel<<<N_NODES, 128>>>(H16, ALS, ALD, b1, O16);

    // --- Layer 2 ---
    h_gemm16_fused<<<M_PAD / 128, 256>>>(O16, W2H, H2, a_s2, a_d2, ALS, ALD);
    agg_final_kernel<<<(N_NODES * 32 + 127) / 128, 128>>>(H2, ALS, ALD, b2, out);
}

// round 11
// speedup vs baseline: 1.0919x; 1.0775x over previous
#include <cuda_runtime.h>
#include <cuda_bf16.h>
#include <cuda_fp16.h>
#include <mma.h>
#include <math.h>
#include <stdint.h>

using namespace nvcuda;

#define N_NODES 50000
#define M_PAD   50048
#define N_EDGES 400000
#define NE_TOT  (N_EDGES + N_NODES)
#define F_IN    128
#define HID     64
#define HEADS   8
#define FEAT    (HEADS * HID)          // 512
#define N_CLASSES 16
#define NEG_SLOPE 0.2f

// ---------------------------------------------------------------------------
// Static scratch
// ---------------------------------------------------------------------------
__device__ __half g_x16 [(size_t)M_PAD * F_IN];
__device__ __half g_O16 [(size_t)M_PAD * FEAT];
__device__ __half g_h16 [(size_t)M_PAD * FEAT];
__device__ __half g_W0h [F_IN * FEAT];
__device__ __half g_W1h [FEAT * FEAT];
__device__ __half g_W2h [FEAT * N_CLASSES];
__device__ float  g_H2  [(size_t)M_PAD * N_CLASSES];
__device__ float  g_als [(size_t)N_NODES * HEADS];
__device__ float  g_ald [(size_t)N_NODES * HEADS];
__device__ int    g_deg   [N_NODES];
__device__ int    g_rowptr[N_NODES + 1];
__device__ int    g_cursor[N_NODES];
__device__ int    g_col   [NE_TOT];
__device__ int    g_bsum  [256];
__device__ int    g_is64;

__device__ __forceinline__ float eluf(float x)   { return x > 0.f ? x : expm1f(x); }
__device__ __forceinline__ float lrelu(float x)  { return x > 0.f ? x : NEG_SLOPE * x; }
__device__ __forceinline__ int clampi(int v) {
    return (v < 0) ? 0 : (v >= N_NODES ? N_NODES - 1 : v);
}
__device__ __forceinline__ int edge_at(const void* ei, int idx, int is64) {
    if (is64) return clampi((int)((const long long*)ei)[idx]);
    return clampi(((const int*)ei)[idx]);
}

__device__ __forceinline__ void cp_async16(uint32_t saddr, const void* gptr, int src_bytes) {
    asm volatile("cp.async.cg.shared.global [%0], [%1], 16, %2;\n"
                 :: "r"(saddr), "l"(gptr), "r"(src_bytes));
}
__device__ __forceinline__ void cp_commit() {
    asm volatile("cp.async.commit_group;\n");
}

// ---------------------------------------------------------------------------
// Setup kernel: fp16 conversions (x, W0, W1, W2) + deg zeroing + dtype probe.
// ---------------------------------------------------------------------------
#define NX4  (N_NODES * F_IN / 4)
#define NW04 (F_IN * FEAT / 4)
#define NW14 (FEAT * FEAT / 4)
#define NW24 (FEAT * N_CLASSES / 4)
#define NSET (NX4 + NW04 + NW14 + NW24 + N_NODES)

__device__ __forceinline__ void cvt4(const float* s, __half* d, int i4) {
    float4 v = *(const float4*)(s + i4);
    *(__half2*)(d + i4)     = __floats2half2_rn(v.x, v.y);
    *(__half2*)(d + i4 + 2) = __floats2half2_rn(v.z, v.w);
}

__global__ void setup_kernel(const float* __restrict__ x,
                             const float* __restrict__ W0,
                             const float* __restrict__ W1,
                             const float* __restrict__ W2,
                             const int* __restrict__ ei_raw)
{
    int i = blockIdx.x * blockDim.x + threadIdx.x;
    if (i == 0) {
        int any_nonzero = 0;
        #pragma unroll 1
        for (int k = 0; k < 64; k++) any_nonzero |= ei_raw[2 * k + 1];
        g_is64 = (any_nonzero == 0) ? 1 : 0;
    }
    if (i < NX4) { cvt4(x, g_x16, i << 2); return; }
    i -= NX4;
    if (i < NW04) { cvt4(W0, g_W0h, i << 2); return; }
    i -= NW04;
    if (i < NW14) { cvt4(W1, g_W1h, i << 2); return; }
    i -= NW14;
    if (i < NW24) { cvt4(W2, g_W2h, i << 2); return; }
    i -= NW24;
    if (i < N_NODES) g_deg[i] = 0;
}

__global__ void count_kernel(const void* __restrict__ ei) {
    int e = blockIdx.x * blockDim.x + threadIdx.x;
    if (e >= NE_TOT) return;
    int is64 = g_is64;
    int dst = (e < N_EDGES) ? edge_at(ei, N_EDGES + e, is64) : (e - N_EDGES);
    atomicAdd(&g_deg[dst], 1);
}

// ---------------------------------------------------------------------------
// Parallel exclusive scan (2 kernels)
// ---------------------------------------------------------------------------
#define SCH 256
#define SNB ((N_NODES + SCH - 1) / SCH)   // 196

__global__ void psum_kernel() {
    int b = blockIdx.x, t = threadIdx.x;
    int i = b * SCH + t;
    int v = (i < N_NODES) ? g_deg[i] : 0;
    __shared__ int ws[8];
    int lane = t & 31, w = t >> 5;
    #pragma unroll
    for (int o = 16; o; o >>= 1) v += __shfl_xor_sync(0xFFFFFFFFu, v, o);
    if (lane == 0) ws[w] = v;
    __syncthreads();
    if (t == 0) {
        int s = 0;
        #pragma unroll
        for (int k = 0; k < 8; k++) s += ws[k];
        g_bsum[b] = s;
    }
}

__global__ void pwrite_kernel() {
    int b = blockIdx.x, t = threadIdx.x;
    __shared__ int ws[8];
    __shared__ int sbase;
    int lane = t & 31, w = t >> 5;

    int pv = (t < b) ? g_bsum[t] : 0;
    int rv = pv;
    #pragma unroll
    for (int o = 16; o; o >>= 1) rv += __shfl_xor_sync(0xFFFFFFFFu, rv, o);
    if (lane == 0) ws[w] = rv;
    __syncthreads();
    if (t == 0) {
        int s = 0;
        #pragma unroll
        for (int k = 0; k < 8; k++) s += ws[k];
        sbase = s;
    }
    __syncthreads();

    int i = b * SCH + t;
    int v = (i < N_NODES) ? g_deg[i] : 0;
    int x = v;
    #pragma unroll
    for (int o = 1; o < 32; o <<= 1) {
        int u = __shfl_up_sync(0xFFFFFFFFu, x, o);
        if (lane >= o) x += u;
    }
    __syncthreads();
    if (lane == 31) ws[w] = x;
    __syncthreads();
    int wbase = 0;
    #pragma unroll
    for (int k = 0; k < 8; k++) if (k < w) wbase += ws[k];
    int excl = sbase + wbase + x - v;
    if (i < N_NODES) {
        g_rowptr[i] = excl;
        g_cursor[i] = excl;
    }
    if (i == N_NODES - 1) g_rowptr[N_NODES] = excl + v;
}

__global__ void fill_kernel(const void* __restrict__ ei) {
    int e = blockIdx.x * blockDim.x + threadIdx.x;
    if (e >= NE_TOT) return;
    int is64 = g_is64;
    int src, dst;
    if (e < N_EDGES) {
        src = edge_at(ei, e, is64);
        dst = edge_at(ei, N_EDGES + e, is64);
    } else {
        src = dst = e - N_EDGES;
    }
    int pos = atomicAdd(&g_cursor[dst], 1);
    if (pos >= 0 && pos < NE_TOT) g_col[pos] = src;
}

// ---------------------------------------------------------------------------
// fp16 HMMA GEMM, 128x128 tile (2 heads), 3-stage cp.async, fused epilogue.
// ---------------------------------------------------------------------------
#define HBM 128
#define HBN 128
#define HBK 32
#define HLA 40
#define HLB 136
#define HST 3
#define STG_LD 72
#define HPOOLB 56832
#define HBS_OFF (HST * HBM * HLA)

template<bool GUARD>
__global__ __launch_bounds__(256) void h_gemm_fused(
    const __half* __restrict__ A, const __half* __restrict__ B,
    int M, int K,
    const float* __restrict__ a_s, const float* __restrict__ a_d,
    float* __restrict__ als, float* __restrict__ ald,
    __half* __restrict__ h16)
{
    __shared__ __align__(16) char pool[HPOOLB];
    __half* Asf = (__half*)pool;
    __half* Bsf = Asf + HBS_OFF;
    float*  stg = (float*)pool;

    const int N = FEAT;
    int tid  = threadIdx.x;
    int warp = tid >> 5;
    int lane = tid & 31;
    int wm   = warp >> 1;
    int wn   = warp & 1;
    int row0 = blockIdx.y * HBM;
    int col0 = blockIdx.x * HBN;

    uint32_t As_a = (uint32_t)__cvta_generic_to_shared(Asf);
    uint32_t Bs_a = (uint32_t)__cvta_generic_to_shared(Bsf);

    wmma::fragment<wmma::accumulator, 16, 16, 16, float> acc[2][4];
    #pragma unroll
    for (int i = 0; i < 2; i++)
        #pragma unroll
        for (int j = 0; j < 4; j++)
            wmma::fill_fragment(acc[i][j], 0.0f);

    const int T = K / HBK;

    auto load_stage = [&](int it) {
        int st = it % HST;
        int k0 = it * HBK;
        {
            int r  = tid >> 1;
            int co = (tid & 1) * 16;
            const __half* gp = A + (size_t)(row0 + r) * K + k0 + co;
            int sb = 16;
            if (GUARD && (row0 + r) >= M) sb = 0;
            uint32_t sa = As_a + (uint32_t)(((st * HBM + r) * HLA + co) * 2);
            cp_async16(sa,      gp,     sb);
            cp_async16(sa + 16, gp + 8, sb);
        }
        {
            int r  = tid >> 3;
            int cq = (tid & 7) * 16;
            const __half* gp = B + (size_t)(k0 + r) * N + col0 + cq;
            uint32_t sa = Bs_a + (uint32_t)(((st * HBK + r) * HLB + cq) * 2);
            cp_async16(sa,      gp,     16);
            cp_async16(sa + 16, gp + 8, 16);
        }
        cp_commit();
    };

    load_stage(0);
    if (T > 1) load_stage(1);
    for (int it = 0; it < T; it++) {
        int cur = it % HST;
        if (it + 2 < T) {
            load_stage(it + 2);
            asm volatile("cp.async.wait_group 2;\n");
        } else if (it + 1 < T) {
            asm volatile("cp.async.wait_group 1;\n");
        } else {
            asm volatile("cp.async.wait_group 0;\n");
        }
        __syncthreads();

        #pragma unroll
        for (int kk = 0; kk < HBK; kk += 16) {
            wmma::fragment<wmma::matrix_a, 16, 16, 16, __half, wmma::row_major> af[2];
            wmma::fragment<wmma::matrix_b, 16, 16, 16, __half, wmma::row_major> bf[4];
            #pragma unroll
            for (int i = 0; i < 2; i++)
                wmma::load_matrix_sync(af[i], Asf + (cur * HBM + wm * 32 + i * 16) * HLA + kk, HLA);
            #pragma unroll
            for (int j = 0; j < 4; j++)
                wmma::load_matrix_sync(bf[j], Bsf + (cur * HBK + kk) * HLB + wn * 64 + j * 16, HLB);
            #pragma unroll
            for (int i = 0; i < 2; i++)
                #pragma unroll
                for (int j = 0; j < 4; j++)
                    wmma::mma_sync(acc[i][j], af[i], bf[j], acc[i][j]);
        }
        __syncthreads();
    }

    #pragma unroll 1
    for (int h = 0; h < 2; h++) {
        if (h == 1) __syncthreads();
        if (wn == h) {
            #pragma unroll
            for (int i = 0; i < 2; i++)
                #pragma unroll
                for (int j = 0; j < 4; j++)
                    wmma::store_matrix_sync(
                        stg + (size_t)(wm * 32 + i * 16) * STG_LD + j * 16,
                        acc[i][j], STG_LD, wmma::mem_row_major);
        }
        __syncthreads();

        int head = (col0 >> 6) + h;
        float as0 = a_s[head * 64 + 2 * lane];
        float as1 = a_s[head * 64 + 2 * lane + 1];
        float ad0 = a_d[head * 64 + 2 * lane];
        float ad1 = a_d[head * 64 + 2 * lane + 1];

        #pragma unroll
        for (int rr = 0; rr < 16; rr++) {
            int r = warp * 16 + rr;
            int grow = row0 + r;
            float2 v = *(const float2*)(stg + (size_t)r * STG_LD + 2 * lane);
            bool ok = (grow < N_NODES);
            if (ok)
                *(__half2*)(h16 + (size_t)grow * FEAT + head * 64 + 2 * lane) =
                    __floats2half2_rn(v.x, v.y);
            float s = fmaf(v.y, as1, v.x * as0);
            float d = fmaf(v.y, ad1, v.x * ad0);
            #pragma unroll
            for (int o = 16; o; o >>= 1) {
                s += __shfl_xor_sync(0xFFFFFFFFu, s, o);
                d += __shfl_xor_sync(0xFFFFFFFFu, d, o);
            }
            if (lane == 0 && ok) {
                als[grow * 8 + head] = s;
                ald[grow * 8 + head] = d;
            }
        }
    }
}

// ---------------------------------------------------------------------------
// Layer-2 fp16 GEMM + fused al2 epilogue.
// ---------------------------------------------------------------------------
__global__ __launch_bounds__(256) void h_gemm16_fused(
    const __half* __restrict__ A, const __half* __restrict__ B,
    float* __restrict__ H2,
    const float* __restrict__ a_s, const float* __restrict__ a_d,
    float* __restrict__ als, float* __restrict__ ald)
{
    __shared__ __align__(16) __half As[128][40];
    __shared__ __align__(16) __half Bs[32][24];
    __shared__ __align__(16) float  stg[128][20];
    int tid  = threadIdx.x;
    int warp = tid >> 5;
    int row0 = blockIdx.x * 128;

    wmma::fragment<wmma::accumulator, 16, 16, 16, float> acc;
    wmma::fill_fragment(acc, 0.0f);

    for (int k0 = 0; k0 < FEAT; k0 += 32) {
        {
            int r  = tid >> 1;
            int co = (tid & 1) * 16;
            const __half* gp = A + (size_t)(row0 + r) * FEAT + k0 + co;
            *(uint4*)(&As[r][co])     = *(const uint4*)(gp);
            *(uint4*)(&As[r][co + 8]) = *(const uint4*)(gp + 8);
        }
        if (tid < 64) {
            int r  = tid >> 1;
            int co = (tid & 1) * 8;
            *(uint4*)(&Bs[r][co]) = *(const uint4*)(B + (size_t)(k0 + r) * 16 + co);
        }
        __syncthreads();
        #pragma unroll
        for (int kk = 0; kk < 32; kk += 16) {
            wmma::fragment<wmma::matrix_a, 16, 16, 16, __half, wmma::row_major> af;
            wmma::fragment<wmma::matrix_b, 16, 16, 16, __half, wmma::row_major> bf;
            wmma::load_matrix_sync(af, &As[warp * 16][kk], 40);
            wmma::load_matrix_sync(bf, &Bs[kk][0], 24);
            wmma::mma_sync(acc, af, bf, acc);
        }
        __syncthreads();
    }

    wmma::store_matrix_sync(&stg[warp * 16][0], acc, 20, wmma::mem_row_major);
    __syncthreads();

    if (tid < 128) {
        int grow = row0 + tid;
        if (grow < N_NODES) {
            float s = 0.f, d = 0.f;
            float* dst = H2 + (size_t)grow * 16;
            #pragma unroll
            for (int c = 0; c < 16; c += 4) {
                float4 v = *(const float4*)(&stg[tid][c]);
                *(float4*)(dst + c) = v;
                s = fmaf(v.x, a_s[c+0], s); d = fmaf(v.x, a_d[c+0], d);
                s = fmaf(v.y, a_s[c+1], s); d = fmaf(v.y, a_d[c+1], d);
                s = fmaf(v.z, a_s[c+2], s); d = fmaf(v.z, a_d[c+2], d);
                s = fmaf(v.w, a_s[c+3], s); d = fmaf(v.w, a_d[c+3], d);
            }
            als[grow] = s;
            ald[grow] = d;
        }
    }
}

// ---------------------------------------------------------------------------
// Softmax + aggregation (H=8, C=64): fp16 gather, self-shifted softmax,
// ELU fused, fp16 output.  (round-8 proven form)
// ---------------------------------------------------------------------------
__global__ __launch_bounds__(128) void agg_kernel(
    const __half* __restrict__ h16, const float* __restrict__ als,
    const float* __restrict__ ald, const float* __restrict__ bias,
    __half* __restrict__ out)
{
    int n = blockIdx.x;
    int t = threadIdx.x;
    int hd = t >> 4;
    int c4 = (t & 15) << 2;
    int start = g_rowptr[n], end = g_rowptr[n + 1];

    float adv = ald[n * 8 + hd];
    float shift = lrelu(als[n * 8 + hd] + adv);

    float4 acc = make_float4(0.f, 0.f, 0.f, 0.f);
    float den = 0.f;
    for (int i = start; i < end; i++) {
        int s = g_col[i];
        float w = __expf(lrelu(als[s * 8 + hd] + adv) - shift);
        den += w;
        uint2 u = *(const uint2*)(h16 + (size_t)s * FEAT + hd * 64 + c4);
        float2 f0 = __half22float2(*reinterpret_cast<__half2*>(&u.x));
        float2 f1 = __half22float2(*reinterpret_cast<__half2*>(&u.y));
        acc.x = fmaf(w, f0.x, acc.x);
        acc.y = fmaf(w, f0.y, acc.y);
        acc.z = fmaf(w, f1.x, acc.z);
        acc.w = fmaf(w, f1.y, acc.w);
    }
    float inv = 1.f / den;
    int c = hd * 64 + c4;
    float r0 = eluf(acc.x * inv + bias[c + 0]);
    float r1 = eluf(acc.y * inv + bias[c + 1]);
    float r2 = eluf(acc.z * inv + bias[c + 2]);
    float r3 = eluf(acc.w * inv + bias[c + 3]);
    __half* op = out + (size_t)n * FEAT + c;
    *(__half2*)(op)     = __floats2half2_rn(r0, r1);
    *(__half2*)(op + 2) = __floats2half2_rn(r2, r3);
}

// Final aggregation (H=1, C=16). One warp per node.
__global__ __launch_bounds__(128) void agg_final_kernel(
    const float* __restrict__ h2, const float* __restrict__ als,
    const float* __restrict__ ald, const float* __restrict__ bias,
    float* __restrict__ out)
{
    int wid = (blockIdx.x * blockDim.x + threadIdx.x) >> 5;
    int lane = threadIdx.x & 31;
    if (wid >= N_NODES) return;
    int n = wid;
    int start = g_rowptr[n], end = g_rowptr[n + 1];
    float adv = ald[n];
    float shift = lrelu(als[n] + adv);
    float acc = 0.f, den = 0.f;
    for (int i = start; i < end; i++) {
        int s = g_col[i];
        float w = __expf(lrelu(als[s] + adv) - shift);
        den += w;
        if (lane < 16) acc = fmaf(w, h2[(size_t)s * 16 + lane], acc);
    }
    if (lane < 16) out[(size_t)n * 16 + lane] = acc / den + bias[lane];
}

// ---------------------------------------------------------------------------
// Launch: CSR build (stream s2) overlapped with GEMM0 (main stream),
// fork-join via events (graph-capture-legal pattern).
// ---------------------------------------------------------------------------
extern "C" void kernel_launch(void* const* d_in, const int* in_sizes, int n_in,
                              void* d_out, int out_size)
{
    const float* x    = (const float*)d_in[0];
    const void*  ei   = d_in[1];
    const float* W0   = (const float*)d_in[2];
    const float* a_s0 = (const float*)d_in[3];
    const float* a_d0 = (const float*)d_in[4];
    const float* b0   = (const float*)d_in[5];
    const float* W1   = (const float*)d_in[6];
    const float* a_s1 = (const float*)d_in[7];
    const float* a_d1 = (const float*)d_in[8];
    const float* b1   = (const float*)d_in[9];
    const float* W2   = (const float*)d_in[10];
    const float* a_s2 = (const float*)d_in[11];
    const float* a_d2 = (const float*)d_in[12];
    const float* b2   = (const float*)d_in[13];
    float*       out  = (float*)d_out;

    float *H2, *ALS, *ALD;
    __half *X16, *O16, *H16, *W0H, *W1H, *W2H;
    cudaGetSymbolAddress((void**)&X16, g_x16);
    cudaGetSymbolAddress((void**)&O16, g_O16);
    cudaGetSymbolAddress((void**)&H16, g_h16);
    cudaGetSymbolAddress((void**)&W0H, g_W0h);
    cudaGetSymbolAddress((void**)&W1H, g_W1h);
    cudaGetSymbolAddress((void**)&W2H, g_W2h);
    cudaGetSymbolAddress((void**)&H2,  g_H2);
    cudaGetSymbolAddress((void**)&ALS, g_als);
    cudaGetSymbolAddress((void**)&ALD, g_ald);

    cudaStream_t s2;
    cudaEvent_t  evFork, evJoin;
    cudaStreamCreateWithFlags(&s2, cudaStreamNonBlocking);
    cudaEventCreateWithFlags(&evFork, cudaEventDisableTiming);
    cudaEventCreateWithFlags(&evJoin, cudaEventDisableTiming);

    // --- setup on main stream (feeds both branches) ---
    setup_kernel<<<(NSET + 255) / 256, 256>>>(x, W0, W1, W2, (const int*)ei);
    cudaEventRecord(evFork, 0);
    cudaStreamWaitEvent(s2, evFork, 0);

    // --- CSR build on s2 (independent of GEMM0) ---
    count_kernel<<<(NE_TOT + 255) / 256, 256, 0, s2>>>(ei);
    psum_kernel<<<SNB, SCH, 0, s2>>>();
    pwrite_kernel<<<SNB, SCH, 0, s2>>>();
    fill_kernel<<<(NE_TOT + 255) / 256, 256, 0, s2>>>(ei);
    cudaEventRecord(evJoin, s2);

    // --- Layer 0 GEMM concurrently on main stream ---
    dim3 gg(FEAT / HBN, M_PAD / HBM);   // (4, 391)
    h_gemm_fused<true><<<gg, 256>>>(X16, W0H, N_NODES, F_IN,
                                    a_s0, a_d0, ALS, ALD, H16);

    // --- join: agg needs CSR + GEMM0 ---
    cudaStreamWaitEvent(0, evJoin, 0);
    agg_kernel<<<N_NODES, 128>>>(H16, ALS, ALD, b0, O16);

    // --- Layer 1 (K=512) ---
    h_gemm_fused<false><<<gg, 256>>>(O16, W1H, M_PAD, FEAT,
                                     a_s1, a_d1, ALS, ALD, H16);
    agg_kernel<<<N_NODES, 128>>>(H16, ALS, ALD, b1, O16);

    // --- Layer 2 ---
    h_gemm16_fused<<<M_PAD / 128, 256>>>(O16, W2H, H2, a_s2, a_d2, ALS, ALD);
    agg_final_kernel<<<(N_NODES * 32 + 127) / 128, 128>>>(H2, ALS, ALD, b2, out);

    cudaEventDestroy(evFork);
    cudaEventDestroy(evJoin);
    cudaStreamDestroy(s2);
}

// round 12
// speedup vs baseline: 1.0979x; 1.0055x over previous
#include <cuda_runtime.h>
#include <cuda_bf16.h>
#include <cuda_fp16.h>
#include <mma.h>
#include <math.h>
#include <stdint.h>

using namespace nvcuda;

#define N_NODES 50000
#define M_PAD   50048
#define N_EDGES 400000
#define NE_TOT  (N_EDGES + N_NODES)
#define F_IN    128
#define HID     64
#define HEADS   8
#define FEAT    (HEADS * HID)          // 512
#define N_CLASSES 16
#define NEG_SLOPE 0.2f

// ---------------------------------------------------------------------------
// Static scratch
// ---------------------------------------------------------------------------
__device__ __half g_x16 [(size_t)M_PAD * F_IN];
__device__ __half g_O16 [(size_t)M_PAD * FEAT];
__device__ __half g_h16 [(size_t)M_PAD * FEAT];
__device__ __half g_W0h [F_IN * FEAT];
__device__ __half g_W1h [FEAT * FEAT];
__device__ __half g_W2h [FEAT * N_CLASSES];
__device__ float  g_H2  [(size_t)M_PAD * N_CLASSES];
__device__ float  g_als [(size_t)N_NODES * HEADS];
__device__ float  g_ald [(size_t)N_NODES * HEADS];
__device__ int    g_deg   [N_NODES];
__device__ int    g_rowptr[N_NODES + 1];
__device__ int    g_cursor[N_NODES];
__device__ int    g_col   [NE_TOT];
__device__ int    g_bsum  [256];
__device__ int    g_is64;

__device__ __forceinline__ float eluf(float x)   { return x > 0.f ? x : expm1f(x); }
__device__ __forceinline__ float lrelu(float x)  { return x > 0.f ? x : NEG_SLOPE * x; }
__device__ __forceinline__ int clampi(int v) {
    return (v < 0) ? 0 : (v >= N_NODES ? N_NODES - 1 : v);
}
__device__ __forceinline__ int edge_at(const void* ei, int idx, int is64) {
    if (is64) return clampi((int)((const long long*)ei)[idx]);
    return clampi(((const int*)ei)[idx]);
}

__device__ __forceinline__ void cp_async16(uint32_t saddr, const void* gptr, int src_bytes) {
    asm volatile("cp.async.cg.shared.global [%0], [%1], 16, %2;\n"
                 :: "r"(saddr), "l"(gptr), "r"(src_bytes));
}
__device__ __forceinline__ void cp_commit() {
    asm volatile("cp.async.commit_group;\n");
}

// ---------------------------------------------------------------------------
// Setup kernel: fp16 conversions (x, W0, W1, W2) + deg zeroing + dtype probe.
// ---------------------------------------------------------------------------
#define NX4  (N_NODES * F_IN / 4)
#define NW04 (F_IN * FEAT / 4)
#define NW14 (FEAT * FEAT / 4)
#define NW24 (FEAT * N_CLASSES / 4)
#define NSET (NX4 + NW04 + NW14 + NW24 + N_NODES)

__device__ __forceinline__ void cvt4(const float* s, __half* d, int i4) {
    float4 v = *(const float4*)(s + i4);
    *(__half2*)(d + i4)     = __floats2half2_rn(v.x, v.y);
    *(__half2*)(d + i4 + 2) = __floats2half2_rn(v.z, v.w);
}

__global__ void setup_kernel(const float* __restrict__ x,
                             const float* __restrict__ W0,
                             const float* __restrict__ W1,
                             const float* __restrict__ W2,
                             const int* __restrict__ ei_raw)
{
    int i = blockIdx.x * blockDim.x + threadIdx.x;
    if (i == 0) {
        int any_nonzero = 0;
        #pragma unroll 1
        for (int k = 0; k < 64; k++) any_nonzero |= ei_raw[2 * k + 1];
        g_is64 = (any_nonzero == 0) ? 1 : 0;
    }
    if (i < NX4) { cvt4(x, g_x16, i << 2); return; }
    i -= NX4;
    if (i < NW04) { cvt4(W0, g_W0h, i << 2); return; }
    i -= NW04;
    if (i < NW14) { cvt4(W1, g_W1h, i << 2); return; }
    i -= NW14;
    if (i < NW24) { cvt4(W2, g_W2h, i << 2); return; }
    i -= NW24;
    if (i < N_NODES) g_deg[i] = 0;
}

__global__ void count_kernel(const void* __restrict__ ei) {
    int e = blockIdx.x * blockDim.x + threadIdx.x;
    if (e >= NE_TOT) return;
    int is64 = g_is64;
    int dst = (e < N_EDGES) ? edge_at(ei, N_EDGES + e, is64) : (e - N_EDGES);
    atomicAdd(&g_deg[dst], 1);
}

// ---------------------------------------------------------------------------
// Parallel exclusive scan (2 kernels)
// ---------------------------------------------------------------------------
#define SCH 256
#define SNB ((N_NODES + SCH - 1) / SCH)   // 196

__global__ void psum_kernel() {
    int b = blockIdx.x, t = threadIdx.x;
    int i = b * SCH + t;
    int v = (i < N_NODES) ? g_deg[i] : 0;
    __shared__ int ws[8];
    int lane = t & 31, w = t >> 5;
    #pragma unroll
    for (int o = 16; o; o >>= 1) v += __shfl_xor_sync(0xFFFFFFFFu, v, o);
    if (lane == 0) ws[w] = v;
    __syncthreads();
    if (t == 0) {
        int s = 0;
        #pragma unroll
        for (int k = 0; k < 8; k++) s += ws[k];
        g_bsum[b] = s;
    }
}

__global__ void pwrite_kernel() {
    int b = blockIdx.x, t = threadIdx.x;
    __shared__ int ws[8];
    __shared__ int sbase;
    int lane = t & 31, w = t >> 5;

    int pv = (t < b) ? g_bsum[t] : 0;
    int rv = pv;
    #pragma unroll
    for (int o = 16; o; o >>= 1) rv += __shfl_xor_sync(0xFFFFFFFFu, rv, o);
    if (lane == 0) ws[w] = rv;
    __syncthreads();
    if (t == 0) {
        int s = 0;
        #pragma unroll
        for (int k = 0; k < 8; k++) s += ws[k];
        sbase = s;
    }
    __syncthreads();

    int i = b * SCH + t;
    int v = (i < N_NODES) ? g_deg[i] : 0;
    int x = v;
    #pragma unroll
    for (int o = 1; o < 32; o <<= 1) {
        int u = __shfl_up_sync(0xFFFFFFFFu, x, o);
        if (lane >= o) x += u;
    }
    __syncthreads();
    if (lane == 31) ws[w] = x;
    __syncthreads();
    int wbase = 0;
    #pragma unroll
    for (int k = 0; k < 8; k++) if (k < w) wbase += ws[k];
    int excl = sbase + wbase + x - v;
    if (i < N_NODES) {
        g_rowptr[i] = excl;
        g_cursor[i] = excl;
    }
    if (i == N_NODES - 1) g_rowptr[N_NODES] = excl + v;
}

__global__ void fill_kernel(const void* __restrict__ ei) {
    int e = blockIdx.x * blockDim.x + threadIdx.x;
    if (e >= NE_TOT) return;
    int is64 = g_is64;
    int src, dst;
    if (e < N_EDGES) {
        src = edge_at(ei, e, is64);
        dst = edge_at(ei, N_EDGES + e, is64);
    } else {
        src = dst = e - N_EDGES;
    }
    int pos = atomicAdd(&g_cursor[dst], 1);
    if (pos >= 0 && pos < NE_TOT) g_col[pos] = src;
}

// ---------------------------------------------------------------------------
// fp16 HMMA GEMM, 128x128 tile (2 heads), 3-stage cp.async, fused epilogue.
// PDL: grid-dependency sync before first global access.
// ---------------------------------------------------------------------------
#define HBM 128
#define HBN 128
#define HBK 32
#define HLA 40
#define HLB 136
#define HST 3
#define STG_LD 72
#define HPOOLB 56832
#define HBS_OFF (HST * HBM * HLA)

template<bool GUARD>
__global__ __launch_bounds__(256) void h_gemm_fused(
    const __half* __restrict__ A, const __half* __restrict__ B,
    int M, int K,
    const float* __restrict__ a_s, const float* __restrict__ a_d,
    float* __restrict__ als, float* __restrict__ ald,
    __half* __restrict__ h16)
{
    __shared__ __align__(16) char pool[HPOOLB];
    __half* Asf = (__half*)pool;
    __half* Bsf = Asf + HBS_OFF;
    float*  stg = (float*)pool;

    const int N = FEAT;
    int tid  = threadIdx.x;
    int warp = tid >> 5;
    int lane = tid & 31;
    int wm   = warp >> 1;
    int wn   = warp & 1;
    int row0 = blockIdx.y * HBM;
    int col0 = blockIdx.x * HBN;

    uint32_t As_a = (uint32_t)__cvta_generic_to_shared(Asf);
    uint32_t Bs_a = (uint32_t)__cvta_generic_to_shared(Bsf);

    wmma::fragment<wmma::accumulator, 16, 16, 16, float> acc[2][4];
    #pragma unroll
    for (int i = 0; i < 2; i++)
        #pragma unroll
        for (int j = 0; j < 4; j++)
            wmma::fill_fragment(acc[i][j], 0.0f);

    // PDL: prologue (above) overlaps producer tail; data access below waits.
    cudaGridDependencySynchronize();

    const int T = K / HBK;

    auto load_stage = [&](int it) {
        int st = it % HST;
        int k0 = it * HBK;
        {
            int r  = tid >> 1;
            int co = (tid & 1) * 16;
            const __half* gp = A + (size_t)(row0 + r) * K + k0 + co;
            int sb = 16;
            if (GUARD && (row0 + r) >= M) sb = 0;
            uint32_t sa = As_a + (uint32_t)(((st * HBM + r) * HLA + co) * 2);
            cp_async16(sa,      gp,     sb);
            cp_async16(sa + 16, gp + 8, sb);
        }
        {
            int r  = tid >> 3;
            int cq = (tid & 7) * 16;
            const __half* gp = B + (size_t)(k0 + r) * N + col0 + cq;
            uint32_t sa = Bs_a + (uint32_t)(((st * HBK + r) * HLB + cq) * 2);
            cp_async16(sa,      gp,     16);
            cp_async16(sa + 16, gp + 8, 16);
        }
        cp_commit();
    };

    load_stage(0);
    if (T > 1) load_stage(1);
    for (int it = 0; it < T; it++) {
        int cur = it % HST;
        if (it + 2 < T) {
            load_stage(it + 2);
            asm volatile("cp.async.wait_group 2;\n");
        } else if (it + 1 < T) {
            asm volatile("cp.async.wait_group 1;\n");
        } else {
            asm volatile("cp.async.wait_group 0;\n");
        }
        __syncthreads();

        #pragma unroll
        for (int kk = 0; kk < HBK; kk += 16) {
            wmma::fragment<wmma::matrix_a, 16, 16, 16, __half, wmma::row_major> af[2];
            wmma::fragment<wmma::matrix_b, 16, 16, 16, __half, wmma::row_major> bf[4];
            #pragma unroll
            for (int i = 0; i < 2; i++)
                wmma::load_matrix_sync(af[i], Asf + (cur * HBM + wm * 32 + i * 16) * HLA + kk, HLA);
            #pragma unroll
            for (int j = 0; j < 4; j++)
                wmma::load_matrix_sync(bf[j], Bsf + (cur * HBK + kk) * HLB + wn * 64 + j * 16, HLB);
            #pragma unroll
            for (int i = 0; i < 2; i++)
                #pragma unroll
                for (int j = 0; j < 4; j++)
                    wmma::mma_sync(acc[i][j], af[i], bf[j], acc[i][j]);
        }
        __syncthreads();
    }

    #pragma unroll 1
    for (int h = 0; h < 2; h++) {
        if (h == 1) __syncthreads();
        if (wn == h) {
            #pragma unroll
            for (int i = 0; i < 2; i++)
                #pragma unroll
                for (int j = 0; j < 4; j++)
                    wmma::store_matrix_sync(
                        stg + (size_t)(wm * 32 + i * 16) * STG_LD + j * 16,
                        acc[i][j], STG_LD, wmma::mem_row_major);
        }
        __syncthreads();

        int head = (col0 >> 6) + h;
        float as0 = a_s[head * 64 + 2 * lane];
        float as1 = a_s[head * 64 + 2 * lane + 1];
        float ad0 = a_d[head * 64 + 2 * lane];
        float ad1 = a_d[head * 64 + 2 * lane + 1];

        #pragma unroll
        for (int rr = 0; rr < 16; rr++) {
            int r = warp * 16 + rr;
            int grow = row0 + r;
            float2 v = *(const float2*)(stg + (size_t)r * STG_LD + 2 * lane);
            bool ok = (grow < N_NODES);
            if (ok)
                *(__half2*)(h16 + (size_t)grow * FEAT + head * 64 + 2 * lane) =
                    __floats2half2_rn(v.x, v.y);
            float s = fmaf(v.y, as1, v.x * as0);
            float d = fmaf(v.y, ad1, v.x * ad0);
            #pragma unroll
            for (int o = 16; o; o >>= 1) {
                s += __shfl_xor_sync(0xFFFFFFFFu, s, o);
                d += __shfl_xor_sync(0xFFFFFFFFu, d, o);
            }
            if (lane == 0 && ok) {
                als[grow * 8 + head] = s;
                ald[grow * 8 + head] = d;
            }
        }
    }
}

// ---------------------------------------------------------------------------
// Layer-2 fp16 GEMM + fused al2 epilogue.
// ---------------------------------------------------------------------------
__global__ __launch_bounds__(256) void h_gemm16_fused(
    const __half* __restrict__ A, const __half* __restrict__ B,
    float* __restrict__ H2,
    const float* __restrict__ a_s, const float* __restrict__ a_d,
    float* __restrict__ als, float* __restrict__ ald)
{
    __shared__ __align__(16) __half As[128][40];
    __shared__ __align__(16) __half Bs[32][24];
    __shared__ __align__(16) float  stg[128][20];
    int tid  = threadIdx.x;
    int warp = tid >> 5;
    int row0 = blockIdx.x * 128;

    wmma::fragment<wmma::accumulator, 16, 16, 16, float> acc;
    wmma::fill_fragment(acc, 0.0f);

    cudaGridDependencySynchronize();

    for (int k0 = 0; k0 < FEAT; k0 += 32) {
        {
            int r  = tid >> 1;
            int co = (tid & 1) * 16;
            const __half* gp = A + (size_t)(row0 + r) * FEAT + k0 + co;
            *(uint4*)(&As[r][co])     = *(const uint4*)(gp);
            *(uint4*)(&As[r][co + 8]) = *(const uint4*)(gp + 8);
        }
        if (tid < 64) {
            int r  = tid >> 1;
            int co = (tid & 1) * 8;
            *(uint4*)(&Bs[r][co]) = *(const uint4*)(B + (size_t)(k0 + r) * 16 + co);
        }
        __syncthreads();
        #pragma unroll
        for (int kk = 0; kk < 32; kk += 16) {
            wmma::fragment<wmma::matrix_a, 16, 16, 16, __half, wmma::row_major> af;
            wmma::fragment<wmma::matrix_b, 16, 16, 16, __half, wmma::row_major> bf;
            wmma::load_matrix_sync(af, &As[warp * 16][kk], 40);
            wmma::load_matrix_sync(bf, &Bs[kk][0], 24);
            wmma::mma_sync(acc, af, bf, acc);
        }
        __syncthreads();
    }

    wmma::store_matrix_sync(&stg[warp * 16][0], acc, 20, wmma::mem_row_major);
    __syncthreads();

    if (tid < 128) {
        int grow = row0 + tid;
        if (grow < N_NODES) {
            float s = 0.f, d = 0.f;
            float* dst = H2 + (size_t)grow * 16;
            #pragma unroll
            for (int c = 0; c < 16; c += 4) {
                float4 v = *(const float4*)(&stg[tid][c]);
                *(float4*)(dst + c) = v;
                s = fmaf(v.x, a_s[c+0], s); d = fmaf(v.x, a_d[c+0], d);
                s = fmaf(v.y, a_s[c+1], s); d = fmaf(v.y, a_d[c+1], d);
                s = fmaf(v.z, a_s[c+2], s); d = fmaf(v.z, a_d[c+2], d);
                s = fmaf(v.w, a_s[c+3], s); d = fmaf(v.w, a_d[c+3], d);
            }
            als[grow] = s;
            ald[grow] = d;
        }
    }
}

// ---------------------------------------------------------------------------
// Softmax + aggregation (H=8, C=64): fp16 gather, self-shifted softmax,
// ELU fused, fp16 output.
// ---------------------------------------------------------------------------
__global__ __launch_bounds__(128) void agg_kernel(
    const __half* __restrict__ h16, const float* __restrict__ als,
    const float* __restrict__ ald, const float* __restrict__ bias,
    __half* __restrict__ out)
{
    int n = blockIdx.x;
    int t = threadIdx.x;
    int hd = t >> 4;
    int c4 = (t & 15) << 2;

    cudaGridDependencySynchronize();

    int start = g_rowptr[n], end = g_rowptr[n + 1];

    float adv = ald[n * 8 + hd];
    float shift = lrelu(als[n * 8 + hd] + adv);

    float4 acc = make_float4(0.f, 0.f, 0.f, 0.f);
    float den = 0.f;
    for (int i = start; i < end; i++) {
        int s = g_col[i];
        float w = __expf(lrelu(als[s * 8 + hd] + adv) - shift);
        den += w;
        uint2 u = *(const uint2*)(h16 + (size_t)s * FEAT + hd * 64 + c4);
        float2 f0 = __half22float2(*reinterpret_cast<__half2*>(&u.x));
        float2 f1 = __half22float2(*reinterpret_cast<__half2*>(&u.y));
        acc.x = fmaf(w, f0.x, acc.x);
        acc.y = fmaf(w, f0.y, acc.y);
        acc.z = fmaf(w, f1.x, acc.z);
        acc.w = fmaf(w, f1.y, acc.w);
    }
    float inv = 1.f / den;
    int c = hd * 64 + c4;
    float r0 = eluf(acc.x * inv + bias[c + 0]);
    float r1 = eluf(acc.y * inv + bias[c + 1]);
    float r2 = eluf(acc.z * inv + bias[c + 2]);
    float r3 = eluf(acc.w * inv + bias[c + 3]);
    __half* op = out + (size_t)n * FEAT + c;
    *(__half2*)(op)     = __floats2half2_rn(r0, r1);
    *(__half2*)(op + 2) = __floats2half2_rn(r2, r3);
}

// Final aggregation (H=1, C=16). One warp per node.
__global__ __launch_bounds__(128) void agg_final_kernel(
    const float* __restrict__ h2, const float* __restrict__ als,
    const float* __restrict__ ald, const float* __restrict__ bias,
    float* __restrict__ out)
{
    int wid = (blockIdx.x * blockDim.x + threadIdx.x) >> 5;
    int lane = threadIdx.x & 31;

    cudaGridDependencySynchronize();

    if (wid >= N_NODES) return;
    int n = wid;
    int start = g_rowptr[n], end = g_rowptr[n + 1];
    float adv = ald[n];
    float shift = lrelu(als[n] + adv);
    float acc = 0.f, den = 0.f;
    for (int i = start; i < end; i++) {
        int s = g_col[i];
        float w = __expf(lrelu(als[s] + adv) - shift);
        den += w;
        if (lane < 16) acc = fmaf(w, h2[(size_t)s * 16 + lane], acc);
    }
    if (lane < 16) out[(size_t)n * 16 + lane] = acc / den + bias[lane];
}

// ---------------------------------------------------------------------------
// PDL launch helper
// ---------------------------------------------------------------------------
template<typename F, typename... Args>
static inline void launch_pdl(F* func, dim3 grid, dim3 block, cudaStream_t st,
                              Args... args) {
    cudaLaunchConfig_t cfg = {};
    cfg.gridDim = grid;
    cfg.blockDim = block;
    cfg.dynamicSmemBytes = 0;
    cfg.stream = st;
    cudaLaunchAttribute attr[1];
    attr[0].id = cudaLaunchAttributeProgrammaticStreamSerialization;
    attr[0].val.programmaticStreamSerializationAllowed = 1;
    cfg.attrs = attr;
    cfg.numAttrs = 1;
    cudaLaunchKernelEx(&cfg, func, args...);
}

// ---------------------------------------------------------------------------
// Launch: CSR on stream s2 overlapped with GEMM0; PDL on the main chain.
// ---------------------------------------------------------------------------
extern "C" void kernel_launch(void* const* d_in, const int* in_sizes, int n_in,
                              void* d_out, int out_size)
{
    const float* x    = (const float*)d_in[0];
    const void*  ei   = d_in[1];
    const float* W0   = (const float*)d_in[2];
    const float* a_s0 = (const float*)d_in[3];
    const float* a_d0 = (const float*)d_in[4];
    const float* b0   = (const float*)d_in[5];
    const float* W1   = (const float*)d_in[6];
    const float* a_s1 = (const float*)d_in[7];
    const float* a_d1 = (const float*)d_in[8];
    const float* b1   = (const float*)d_in[9];
    const float* W2   = (const float*)d_in[10];
    const float* a_s2 = (const float*)d_in[11];
    const float* a_d2 = (const float*)d_in[12];
    const float* b2   = (const float*)d_in[13];
    float*       out  = (float*)d_out;

    float *H2, *ALS, *ALD;
    __half *X16, *O16, *H16, *W0H, *W1H, *W2H;
    cudaGetSymbolAddress((void**)&X16, g_x16);
    cudaGetSymbolAddress((void**)&O16, g_O16);
    cudaGetSymbolAddress((void**)&H16, g_h16);
    cudaGetSymbolAddress((void**)&W0H, g_W0h);
    cudaGetSymbolAddress((void**)&W1H, g_W1h);
    cudaGetSymbolAddress((void**)&W2H, g_W2h);
    cudaGetSymbolAddress((void**)&H2,  g_H2);
    cudaGetSymbolAddress((void**)&ALS, g_als);
    cudaGetSymbolAddress((void**)&ALD, g_ald);

    cudaStream_t s2;
    cudaEvent_t  evFork, evJoin;
    cudaStreamCreateWithFlags(&s2, cudaStreamNonBlocking);
    cudaEventCreateWithFlags(&evFork, cudaEventDisableTiming);
    cudaEventCreateWithFlags(&evJoin, cudaEventDisableTiming);

    // --- setup on main stream (feeds both branches) ---
    setup_kernel<<<(NSET + 255) / 256, 256>>>(x, W0, W1, W2, (const int*)ei);
    cudaEventRecord(evFork, 0);
    cudaStreamWaitEvent(s2, evFork, 0);

    // --- CSR build on s2 (independent of GEMM0) ---
    count_kernel<<<(NE_TOT + 255) / 256, 256, 0, s2>>>(ei);
    psum_kernel<<<SNB, SCH, 0, s2>>>();
    pwrite_kernel<<<SNB, SCH, 0, s2>>>();
    fill_kernel<<<(NE_TOT + 255) / 256, 256, 0, s2>>>(ei);
    cudaEventRecord(evJoin, s2);

    dim3 gg(FEAT / HBN, M_PAD / HBM);   // (4, 391)
    dim3 b256(256, 1, 1), b128(128, 1, 1);

    // --- Layer 0 GEMM (PDL after setup) ---
    launch_pdl(&h_gemm_fused<true>, gg, b256, (cudaStream_t)0,
               (const __half*)X16, (const __half*)W0H, (int)N_NODES, (int)F_IN,
               a_s0, a_d0, (float*)ALS, (float*)ALD, (__half*)H16);

    // --- join: agg needs CSR + GEMM0 ---
    cudaStreamWaitEvent(0, evJoin, 0);
    launch_pdl(&agg_kernel, dim3(N_NODES, 1, 1), b128, (cudaStream_t)0,
               (const __half*)H16, (const float*)ALS, (const float*)ALD, b0,
               (__half*)O16);

    // --- Layer 1 (K=512) ---
    launch_pdl(&h_gemm_fused<false>, gg, b256, (cudaStream_t)0,
               (const __half*)O16, (const __half*)W1H, (int)M_PAD, (int)FEAT,
               a_s1, a_d1, (float*)ALS, (float*)ALD, (__half*)H16);
    launch_pdl(&agg_kernel, dim3(N_NODES, 1, 1), b128, (cudaStream_t)0,
               (const __half*)H16, (const float*)ALS, (const float*)ALD, b1,
               (__half*)O16);

    // --- Layer 2 ---
    launch_pdl(&h_gemm16_fused, dim3(M_PAD / 128, 1, 1), b256, (cudaStream_t)0,
               (const __half*)O16, (const __half*)W2H, (float*)H2,
               a_s2, a_d2, (float*)ALS, (float*)ALD);
    launch_pdl(&agg_final_kernel, dim3((N_NODES * 32 + 127) / 128, 1, 1), b128,
               (cudaStream_t)0,
               (const float*)H2, (const float*)ALS, (const float*)ALD, b2, out);

    cudaEventDestroy(evFork);
    cudaEventDestroy(evJoin);
    cudaStreamDestroy(s2);
}